// round 2
// baseline (speedup 1.0000x reference)
#include <cuda_runtime.h>
#include <math.h>

#define BATCH  2048
#define DMODEL 256
#define NFEAT  32768
#define NBLK   8

// ---------------- device scratch (static: no runtime allocation) ----------------
__device__ float g_acts[(size_t)BATCH * NFEAT];   // 256 MiB
__device__ float g_wdn[NFEAT];
__device__ float g_perfeat[NFEAT];                // sum over batch of log terms
__device__ float g_err[NBLK];
__device__ unsigned long long g_l0;
__device__ float g_normsum;
__device__ float g_scale;
__device__ int   g_ends[NBLK];

// ---------------- init: zero accumulators (must be deterministic per replay) ----
__global__ void k_init() {
    int i = blockIdx.x * blockDim.x + threadIdx.x;
    if (i < NFEAT) g_perfeat[i] = 0.f;
    if (i < NBLK)  g_err[i] = 0.f;
    if (i == 0) { g_l0 = 0ull; g_normsum = 0.f; }
}

// ---------------- W_dec row norms: one warp per feature row ----------------
__global__ void k_wdnorm(const float* __restrict__ Wd) {
    int warp = (blockIdx.x * blockDim.x + threadIdx.x) >> 5;
    int lane = threadIdx.x & 31;
    if (warp >= NFEAT) return;
    const float* row = Wd + (size_t)warp * DMODEL;
    float s = 0.f;
    #pragma unroll
    for (int i = lane; i < DMODEL; i += 32) { float v = row[i]; s = fmaf(v, v, s); }
    #pragma unroll
    for (int o = 16; o; o >>= 1) s += __shfl_xor_sync(0xffffffffu, s, o);
    if (!lane) g_wdn[warp] = sqrtf(s);
}

// ---------------- sum of row L2 norms of x: one warp per batch row -------------
__global__ void k_rownorm(const float* __restrict__ x) {
    int warp = (blockIdx.x * blockDim.x + threadIdx.x) >> 5;
    int lane = threadIdx.x & 31;
    if (warp >= BATCH) return;
    const float* row = x + (size_t)warp * DMODEL;
    float s = 0.f;
    #pragma unroll
    for (int i = lane; i < DMODEL; i += 32) { float v = row[i]; s = fmaf(v, v, s); }
    #pragma unroll
    for (int o = 16; o; o >>= 1) s += __shfl_xor_sync(0xffffffffu, s, o);
    if (!lane) atomicAdd(&g_normsum, sqrtf(s));
}

// ---------------- finalize normalizer scale ----------------
__global__ void k_scale(const float* __restrict__ ra) {
    float mean = g_normsum / (float)BATCH;
    float r = 0.99f * ra[0] + 0.01f * mean;
    g_scale = 16.0f / r;   // sqrt(256) / ra
}

// ---------------- segment boundary extraction (seg is non-decreasing) ----------
__global__ void k_bounds(const int* __restrict__ seg) {
    int f = blockIdx.x * blockDim.x + threadIdx.x;
    if (f >= NFEAT) return;
    int s  = seg[f];
    int sn = (f + 1 < NFEAT) ? seg[f + 1] : NBLK;
    for (int j = s; j < sn; j++) g_ends[j] = f + 1;
}

// ---------------- encoder GEMM + relu + log-sum + L0, stores acts --------------
// C[2048, 32768] tile 64x64, 256 threads, thread tile 4x4, k-chunk 32.
__global__ void __launch_bounds__(256) k_encoder(const float* __restrict__ x,
                                                 const float* __restrict__ We,
                                                 const float* __restrict__ be) {
    __shared__ float As[32][68];     // transposed A tile: As[k][m]
    __shared__ float Bs[32][64];     // Bs[k][n]
    __shared__ float colsum[64];
    __shared__ int   redc[8];

    const int tid = threadIdx.x;
    const int tx = tid & 15, ty = tid >> 4;
    const int m0 = blockIdx.y * 64, n0 = blockIdx.x * 64;

    float acc[4][4] = {};

    for (int kb = 0; kb < DMODEL; kb += 32) {
        // A: 64x32, coalesced load (k fastest), transposed store
        #pragma unroll
        for (int it = 0; it < 8; ++it) {
            int idx = tid + it * 256;           // 0..2047
            int k = idx & 31, m = idx >> 5;
            As[k][m] = x[(size_t)(m0 + m) * DMODEL + kb + k];
        }
        // B: 32x64 via float4
        #pragma unroll
        for (int it = 0; it < 2; ++it) {
            int idx = tid + it * 256;           // 0..511 float4s
            int k = idx >> 4, nq = idx & 15;
            *(float4*)&Bs[k][nq * 4] =
                *(const float4*)&We[(size_t)(kb + k) * NFEAT + n0 + nq * 4];
        }
        __syncthreads();
        #pragma unroll
        for (int kk = 0; kk < 32; ++kk) {
            float4 a4 = *(float4*)&As[kk][ty * 4];
            float4 b4 = *(float4*)&Bs[kk][tx * 4];
            float av[4] = {a4.x, a4.y, a4.z, a4.w};
            float bv[4] = {b4.x, b4.y, b4.z, b4.w};
            #pragma unroll
            for (int i = 0; i < 4; ++i)
                #pragma unroll
                for (int j = 0; j < 4; ++j)
                    acc[i][j] = fmaf(av[i], bv[j], acc[i][j]);
        }
        __syncthreads();
    }

    // epilogue: relu(acc*s + b), store acts, per-feature log-sum, L0 count
    float s = g_scale;
    if (tid < 64) colsum[tid] = 0.f;
    __syncthreads();

    float act[4][4];
    int cnt = 0;
    #pragma unroll
    for (int j = 0; j < 4; ++j) {
        int c = n0 + tx * 4 + j;
        float bias = be[c];
        float wd10 = g_wdn[c] * 10.0f;
        float lsum = 0.f;
        #pragma unroll
        for (int i = 0; i < 4; ++i) {
            float a = fmaxf(fmaf(acc[i][j], s, bias), 0.f);
            act[i][j] = a;
            cnt += (a > 0.f) ? 1 : 0;
            lsum += __logf(fmaf(a, wd10, 1.0f));   // log(a*wdn+0.1)-log(0.1)
        }
        atomicAdd(&colsum[tx * 4 + j], lsum);
    }
    #pragma unroll
    for (int i = 0; i < 4; ++i) {
        float4 v = make_float4(act[i][0], act[i][1], act[i][2], act[i][3]);
        *(float4*)&g_acts[(size_t)(m0 + ty * 4 + i) * NFEAT + n0 + tx * 4] = v;
    }
    __syncthreads();
    if (tid < 64) atomicAdd(&g_perfeat[n0 + tid], colsum[tid]);

    #pragma unroll
    for (int o = 16; o; o >>= 1) cnt += __shfl_xor_sync(0xffffffffu, cnt, o);
    if ((tid & 31) == 0) redc[tid >> 5] = cnt;
    __syncthreads();
    if (tid == 0) {
        int t = 0;
        #pragma unroll
        for (int w = 0; w < 8; ++w) t += redc[w];
        atomicAdd(&g_l0, (unsigned long long)t);
    }
}

// ---------------- decoder: K-partitioned GEMM with boundary error snapshots ----
// acts[2048,32768] @ W_dec[32768,256]; M-tile 16, N=256 (full), k-chunk 16.
// Accumulator never resets -> cumsum over blocks is automatic.
// smem: Xs 16K + Ws 16K + Ac 1.25K + bds 1K + misc < 48K static limit.
__global__ void __launch_bounds__(256) k_decoder(const float* __restrict__ x,
                                                 const float* __restrict__ Wd,
                                                 const float* __restrict__ bd) {
    __shared__ float Xs[16][256];   // xn tile (16 KB)
    __shared__ float Ws[16][256];   // W_dec chunk (16 KB)
    __shared__ float Ac[16][20];    // transposed acts chunk: Ac[k][r] (pad 20)
    __shared__ float bds[256];
    __shared__ int   ends_s[9];
    __shared__ float redw[8];

    const int tid = threadIdx.x;
    const int tx = tid & 63, ty = tid >> 6;
    const int row0 = blockIdx.x * 16;
    const int c0 = tx * 4, r0 = ty * 4;

    if (tid < 8) ends_s[tid] = g_ends[tid];
    if (tid == 8) ends_s[8] = 0x7fffffff;
    bds[tid] = bd[tid];

    float s = g_scale;
    #pragma unroll
    for (int it = 0; it < 4; ++it) {
        int idx = tid + it * 256;    // 0..1023 float4s over 16x256
        int r = idx >> 6, cq = idx & 63;
        float4 v = *(const float4*)&x[(size_t)(row0 + r) * DMODEL + cq * 4];
        v.x *= s; v.y *= s; v.z *= s; v.w *= s;
        *(float4*)&Xs[r][cq * 4] = v;
    }

    float acc[4][4] = {};
    int nb = 0;
    __syncthreads();

    for (int kb = 0; kb < NFEAT; kb += 16) {
        // Ws: 16x256 floats = 1024 float4, 4 iters
        #pragma unroll
        for (int it = 0; it < 4; ++it) {
            int idx = tid + it * 256;   // 0..1023 float4s over 16x256
            int k = idx >> 6, cq = idx & 63;
            *(float4*)&Ws[k][cq * 4] =
                *(const float4*)&Wd[(size_t)(kb + k) * DMODEL + cq * 4];
        }
        // Ac: 16 rows x 16 k = 256 elements, 1 per thread
        {
            int k = tid & 15, r = tid >> 4;
            if (r < 16) Ac[k][r] = g_acts[(size_t)(row0 + r) * NFEAT + kb + k];
        }
        __syncthreads();

        if (ends_s[nb] > kb + 16) {
            // hot path: no segment boundary in this chunk
            #pragma unroll
            for (int kk = 0; kk < 16; ++kk) {
                float4 a4 = *(float4*)&Ac[kk][r0];
                float4 b4 = *(float4*)&Ws[kk][c0];
                float av[4] = {a4.x, a4.y, a4.z, a4.w};
                float bv[4] = {b4.x, b4.y, b4.z, b4.w};
                #pragma unroll
                for (int i = 0; i < 4; ++i)
                    #pragma unroll
                    for (int j = 0; j < 4; ++j)
                        acc[i][j] = fmaf(av[i], bv[j], acc[i][j]);
            }
        } else {
            // boundary chunk: step k one at a time, emit error at each boundary
            for (int kk = 0; kk < 16; ++kk) {
                float4 a4 = *(float4*)&Ac[kk][r0];
                float4 b4 = *(float4*)&Ws[kk][c0];
                float av[4] = {a4.x, a4.y, a4.z, a4.w};
                float bv[4] = {b4.x, b4.y, b4.z, b4.w};
                #pragma unroll
                for (int i = 0; i < 4; ++i)
                    #pragma unroll
                    for (int j = 0; j < 4; ++j)
                        acc[i][j] = fmaf(av[i], bv[j], acc[i][j]);

                int kg = kb + kk + 1;
                while (nb < NBLK && ends_s[nb] == kg) {
                    float e = 0.f;
                    #pragma unroll
                    for (int i = 0; i < 4; ++i)
                        #pragma unroll
                        for (int j = 0; j < 4; ++j) {
                            float dlt = acc[i][j] + bds[c0 + j] - Xs[r0 + i][c0 + j];
                            e = fmaf(dlt, dlt, e);
                        }
                    #pragma unroll
                    for (int o = 16; o; o >>= 1) e += __shfl_xor_sync(0xffffffffu, e, o);
                    if ((tid & 31) == 0) redw[tid >> 5] = e;
                    __syncthreads();
                    if (tid == 0) {
                        float t = 0.f;
                        #pragma unroll
                        for (int w = 0; w < 8; ++w) t += redw[w];
                        atomicAdd(&g_err[nb], t);
                    }
                    __syncthreads();
                    nb++;
                }
            }
        }
        __syncthreads();
    }
}

// ---------------- final combine: segment-sum, cumsum, l0 controller, loss ------
__global__ void k_final(const int* __restrict__ seg, const float* __restrict__ bw,
                        const float* __restrict__ l1s, float* __restrict__ out) {
    const int tid = threadIdx.x;
    float a[NBLK] = {};
    for (int f = tid; f < NFEAT; f += 256) {
        float v = g_perfeat[f];
        int sg = seg[f];
        #pragma unroll
        for (int k = 0; k < NBLK; ++k)
            if (sg == k) a[k] += v;
    }
    __shared__ float red[8];
    __shared__ float bl[NBLK];
    for (int k = 0; k < NBLK; ++k) {
        float v = a[k];
        #pragma unroll
        for (int o = 16; o; o >>= 1) v += __shfl_xor_sync(0xffffffffu, v, o);
        if ((tid & 31) == 0) red[tid >> 5] = v;
        __syncthreads();
        if (tid == 0) {
            float t = 0.f;
            for (int w = 0; w < 8; ++w) t += red[w];
            bl[k] = t;
        }
        __syncthreads();
    }
    if (tid == 0) {
        float cum = 0.f, l1 = 0.f;
        for (int k = 0; k < NBLK; ++k) { cum += bl[k]; l1 += bw[k] * cum; }
        l1 = l1 / (8.0f * (float)BATCH);          // mean over batch then mean over K
        float mse = 0.f;
        for (int k = 0; k < NBLK; ++k) mse += bw[k] * g_err[k];
        mse = mse / (8.0f * (float)BATCH);
        float l0 = (float)g_l0 / (float)BATCH;
        float ls = l1s[0] * (l0 < 100.0f ? (1.0f - 3e-4f) : (1.0f + 3e-4f));
        out[0] = mse + ls * l1;
    }
}

// ---------------- launch ----------------
extern "C" void kernel_launch(void* const* d_in, const int* in_sizes, int n_in,
                              void* d_out, int out_size) {
    const float* x   = (const float*)d_in[0];
    const float* We  = (const float*)d_in[1];
    const float* be  = (const float*)d_in[2];
    const float* Wd  = (const float*)d_in[3];
    const float* bd  = (const float*)d_in[4];
    const float* bw  = (const float*)d_in[5];
    const float* ra  = (const float*)d_in[6];
    const float* l1s = (const float*)d_in[7];
    const int*   seg = (const int*)d_in[8];
    float* out = (float*)d_out;

    k_init<<<128, 256>>>();
    k_wdnorm<<<(NFEAT * 32) / 256, 256>>>(Wd);
    k_rownorm<<<(BATCH * 32) / 256, 256>>>(x);
    k_scale<<<1, 1>>>(ra);
    k_bounds<<<NFEAT / 256, 256>>>(seg);
    k_encoder<<<dim3(NFEAT / 64, BATCH / 64), 256>>>(x, We, be);
    k_decoder<<<BATCH / 16, 256>>>(x, Wd, bd);
    k_final<<<1, 256>>>(seg, bw, l1s, out);
}

// round 3
// speedup vs baseline: 2.2395x; 2.2395x over previous
#include <cuda_runtime.h>
#include <math.h>

#define BATCH  2048
#define DMODEL 256
#define NFEAT  32768
#define NBLK   8

// ---------------- device scratch ----------------
__device__ float g_acts[(size_t)BATCH * NFEAT];          // 256 MiB
__device__ float g_G[(size_t)NBLK * BATCH * DMODEL];     // 16 MiB per-segment deltas
__device__ float g_wdn[NFEAT];
__device__ float g_perfeat[NFEAT];
__device__ float g_msesum;
__device__ unsigned long long g_l0;
__device__ float g_normsum;
__device__ float g_scale;
__device__ int   g_ends[NBLK];

// ---------------- init ----------------
__global__ void k_init() {
    int i = blockIdx.x * blockDim.x + threadIdx.x;
    if (i < NFEAT) g_perfeat[i] = 0.f;
    if (i == 0) { g_l0 = 0ull; g_normsum = 0.f; g_msesum = 0.f; }
}

__global__ void k_zeroG() {
    size_t i = (size_t)(blockIdx.x * blockDim.x + threadIdx.x) * 4;
    *(float4*)&g_G[i] = make_float4(0.f, 0.f, 0.f, 0.f);
}

// ---------------- W_dec row norms ----------------
__global__ void k_wdnorm(const float* __restrict__ Wd) {
    int warp = (blockIdx.x * blockDim.x + threadIdx.x) >> 5;
    int lane = threadIdx.x & 31;
    if (warp >= NFEAT) return;
    const float* row = Wd + (size_t)warp * DMODEL;
    float s = 0.f;
    #pragma unroll
    for (int i = lane; i < DMODEL; i += 32) { float v = row[i]; s = fmaf(v, v, s); }
    #pragma unroll
    for (int o = 16; o; o >>= 1) s += __shfl_xor_sync(0xffffffffu, s, o);
    if (!lane) g_wdn[warp] = sqrtf(s);
}

// ---------------- sum of row L2 norms of x ----------------
__global__ void k_rownorm(const float* __restrict__ x) {
    int warp = (blockIdx.x * blockDim.x + threadIdx.x) >> 5;
    int lane = threadIdx.x & 31;
    if (warp >= BATCH) return;
    const float* row = x + (size_t)warp * DMODEL;
    float s = 0.f;
    #pragma unroll
    for (int i = lane; i < DMODEL; i += 32) { float v = row[i]; s = fmaf(v, v, s); }
    #pragma unroll
    for (int o = 16; o; o >>= 1) s += __shfl_xor_sync(0xffffffffu, s, o);
    if (!lane) atomicAdd(&g_normsum, sqrtf(s));
}

__global__ void k_scale(const float* __restrict__ ra) {
    float mean = g_normsum / (float)BATCH;
    float r = 0.99f * ra[0] + 0.01f * mean;
    g_scale = 16.0f / r;
}

// ---------------- segment ends (seg non-decreasing) ----------------
__global__ void k_bounds(const int* __restrict__ seg) {
    int f = blockIdx.x * blockDim.x + threadIdx.x;
    if (f >= NFEAT) return;
    int s  = seg[f];
    int sn = (f + 1 < NFEAT) ? seg[f + 1] : NBLK;
    for (int j = s; j < sn; j++) g_ends[j] = f + 1;
}

// =====================================================================
// Encoder: C[2048,32768] = relu(s*(x@We)+be); tile 128x128, micro 8x8,
// k-chunk 16, double-buffered. Fused log-sum / L0 epilogue, stores acts.
// =====================================================================
__global__ void __launch_bounds__(256) k_encoder(const float* __restrict__ x,
                                                 const float* __restrict__ We,
                                                 const float* __restrict__ be) {
    __shared__ float As[2][16][132];     // As[buf][k][m]
    __shared__ float Bs[2][16][128];     // Bs[buf][k][n]
    __shared__ float colpart[16][128];
    __shared__ int   redc[8];

    const int tid = threadIdx.x;
    const int tx = tid & 15, ty = tid >> 4;
    const int c0 = tx * 8, r0 = ty * 8;
    const int n0 = blockIdx.x * 128, m0 = blockIdx.y * 128;

    // load index precompute
    const int am0 = tid >> 2, ak0 = (tid & 3) * 4;   // A: 512 float4 over 128x16
    const int am1 = am0 + 64;
    const int bk0 = tid >> 5, bn0 = (tid & 31) * 4;  // B: 512 float4 over 16x128
    const int bk1 = bk0 + 8;

    float4 fa0, fa1, fb0, fb1;

    auto fetch = [&](int kb) {
        fa0 = *(const float4*)&x[(size_t)(m0 + am0) * DMODEL + kb + ak0];
        fa1 = *(const float4*)&x[(size_t)(m0 + am1) * DMODEL + kb + ak0];
        fb0 = *(const float4*)&We[(size_t)(kb + bk0) * NFEAT + n0 + bn0];
        fb1 = *(const float4*)&We[(size_t)(kb + bk1) * NFEAT + n0 + bn0];
    };
    auto stage = [&](int s) {
        As[s][ak0 + 0][am0] = fa0.x; As[s][ak0 + 1][am0] = fa0.y;
        As[s][ak0 + 2][am0] = fa0.z; As[s][ak0 + 3][am0] = fa0.w;
        As[s][ak0 + 0][am1] = fa1.x; As[s][ak0 + 1][am1] = fa1.y;
        As[s][ak0 + 2][am1] = fa1.z; As[s][ak0 + 3][am1] = fa1.w;
        *(float4*)&Bs[s][bk0][bn0] = fb0;
        *(float4*)&Bs[s][bk1][bn0] = fb1;
    };

    float acc[8][8] = {};

    fetch(0); stage(0); __syncthreads();

    #pragma unroll 1
    for (int c = 0; c < 16; ++c) {
        int s = c & 1;
        if (c < 15) fetch((c + 1) * 16);
        #pragma unroll
        for (int kk = 0; kk < 16; ++kk) {
            float a[8], b[8];
            *(float4*)&a[0] = *(float4*)&As[s][kk][r0];
            *(float4*)&a[4] = *(float4*)&As[s][kk][r0 + 4];
            *(float4*)&b[0] = *(float4*)&Bs[s][kk][c0];
            *(float4*)&b[4] = *(float4*)&Bs[s][kk][c0 + 4];
            #pragma unroll
            for (int i = 0; i < 8; ++i)
                #pragma unroll
                for (int j = 0; j < 8; ++j)
                    acc[i][j] = fmaf(a[i], b[j], acc[i][j]);
        }
        if (c < 15) stage(s ^ 1);
        __syncthreads();
    }

    // epilogue
    float sc = g_scale;
    int cnt = 0;
    #pragma unroll
    for (int j = 0; j < 8; ++j) {
        int cc = n0 + c0 + j;
        float bias = be[cc];
        float wd10 = g_wdn[cc] * 10.0f;
        float lsum = 0.f;
        #pragma unroll
        for (int i = 0; i < 8; ++i) {
            float a = fmaxf(fmaf(acc[i][j], sc, bias), 0.f);
            acc[i][j] = a;
            cnt += (a > 0.f) ? 1 : 0;
            lsum += __logf(fmaf(a, wd10, 1.0f));
        }
        colpart[ty][c0 + j] = lsum;
    }
    // store acts
    #pragma unroll
    for (int i = 0; i < 8; ++i) {
        float* dst = &g_acts[(size_t)(m0 + r0 + i) * NFEAT + n0 + c0];
        *(float4*)&dst[0] = make_float4(acc[i][0], acc[i][1], acc[i][2], acc[i][3]);
        *(float4*)&dst[4] = make_float4(acc[i][4], acc[i][5], acc[i][6], acc[i][7]);
    }
    __syncthreads();
    if (tid < 128) {
        float t = 0.f;
        #pragma unroll
        for (int w = 0; w < 16; ++w) t += colpart[w][tid];
        atomicAdd(&g_perfeat[n0 + tid], t);
    }
    #pragma unroll
    for (int o = 16; o; o >>= 1) cnt += __shfl_xor_sync(0xffffffffu, cnt, o);
    if ((tid & 31) == 0) redc[tid >> 5] = cnt;
    __syncthreads();
    if (tid == 0) {
        int t = 0;
        #pragma unroll
        for (int w = 0; w < 8; ++w) t += redc[w];
        atomicAdd(&g_l0, (unsigned long long)t);
    }
}

// =====================================================================
// Decoder split-K: acts[2048,32768] @ Wd[32768,256], grid (KS=16, NT=2, MT=16).
// Tile 128x128(M,N), micro 8x8, k-chunk 16, double-buffered.
// At each segment boundary in this block's K-range, flush acc into g_G[j].
// =====================================================================
__global__ void __launch_bounds__(256) k_decoder(const float* __restrict__ Wd) {
    __shared__ float As[2][16][132];   // acts^T chunk
    __shared__ float Bs[2][16][128];   // Wd chunk
    __shared__ int   ends_s[9];

    const int tid = threadIdx.x;
    const int tx = tid & 15, ty = tid >> 4;
    const int c0 = tx * 8, r0 = ty * 8;
    const int ks     = blockIdx.x * 2048;       // K-range start
    const int n_base = blockIdx.y * 128;
    const int r_base = blockIdx.z * 128;

    if (tid < 8) ends_s[tid] = g_ends[tid];
    if (tid == 8) ends_s[8] = 0x7fffffff;

    const int am0 = tid >> 2, ak0 = (tid & 3) * 4;
    const int am1 = am0 + 64;
    const int bk0 = tid >> 5, bn0 = (tid & 31) * 4;
    const int bk1 = bk0 + 8;

    float4 fa0, fa1, fb0, fb1;
    auto fetch = [&](int kb) {
        fa0 = *(const float4*)&g_acts[(size_t)(r_base + am0) * NFEAT + kb + ak0];
        fa1 = *(const float4*)&g_acts[(size_t)(r_base + am1) * NFEAT + kb + ak0];
        fb0 = *(const float4*)&Wd[(size_t)(kb + bk0) * DMODEL + n_base + bn0];
        fb1 = *(const float4*)&Wd[(size_t)(kb + bk1) * DMODEL + n_base + bn0];
    };
    auto stage = [&](int s) {
        As[s][ak0 + 0][am0] = fa0.x; As[s][ak0 + 1][am0] = fa0.y;
        As[s][ak0 + 2][am0] = fa0.z; As[s][ak0 + 3][am0] = fa0.w;
        As[s][ak0 + 0][am1] = fa1.x; As[s][ak0 + 1][am1] = fa1.y;
        As[s][ak0 + 2][am1] = fa1.z; As[s][ak0 + 3][am1] = fa1.w;
        *(float4*)&Bs[s][bk0][bn0] = fb0;
        *(float4*)&Bs[s][bk1][bn0] = fb1;
    };

    float acc[8][8] = {};
    __syncthreads();   // ends_s visible

    int je = 0;
    while (ends_s[je] <= ks) je++;

    auto flush = [&](int j) {
        float* Gp = &g_G[(size_t)j * (BATCH * DMODEL)
                         + (size_t)(r_base + r0) * DMODEL + n_base + c0];
        #pragma unroll
        for (int i = 0; i < 8; ++i)
            #pragma unroll
            for (int jj = 0; jj < 8; ++jj) {
                atomicAdd(&Gp[(size_t)i * DMODEL + jj], acc[i][jj]);
                acc[i][jj] = 0.f;
            }
    };

    fetch(ks); stage(0); __syncthreads();

    #pragma unroll 1
    for (int c = 0; c < 128; ++c) {
        int s = c & 1;
        int kb = ks + c * 16;
        if (c < 127) fetch(kb + 16);

        if (ends_s[je] > kb + 16) {
            // hot: no boundary here
            #pragma unroll
            for (int kk = 0; kk < 16; ++kk) {
                float a[8], b[8];
                *(float4*)&a[0] = *(float4*)&As[s][kk][r0];
                *(float4*)&a[4] = *(float4*)&As[s][kk][r0 + 4];
                *(float4*)&b[0] = *(float4*)&Bs[s][kk][c0];
                *(float4*)&b[4] = *(float4*)&Bs[s][kk][c0 + 4];
                #pragma unroll
                for (int i = 0; i < 8; ++i)
                    #pragma unroll
                    for (int j = 0; j < 8; ++j)
                        acc[i][j] = fmaf(a[i], b[j], acc[i][j]);
            }
        } else {
            for (int kk = 0; kk < 16; ++kk) {
                float a[8], b[8];
                *(float4*)&a[0] = *(float4*)&As[s][kk][r0];
                *(float4*)&a[4] = *(float4*)&As[s][kk][r0 + 4];
                *(float4*)&b[0] = *(float4*)&Bs[s][kk][c0];
                *(float4*)&b[4] = *(float4*)&Bs[s][kk][c0 + 4];
                #pragma unroll
                for (int i = 0; i < 8; ++i)
                    #pragma unroll
                    for (int j = 0; j < 8; ++j)
                        acc[i][j] = fmaf(a[i], b[j], acc[i][j]);
                int kg = kb + kk + 1;
                while (ends_s[je] == kg) { flush(je); je++; }
            }
        }
        if (c < 127) stage(s ^ 1);
        __syncthreads();
    }
    if (je < NBLK) flush(je);   // residual for the segment containing range end
}

// ---------------- cumsum over segments + weighted squared error ----------------
__global__ void k_errs(const float* __restrict__ x, const float* __restrict__ bd,
                       const float* __restrict__ bw) {
    const int tid = threadIdx.x;
    int idx = blockIdx.x * 256 + tid;            // over 2048*256
    int c = idx & (DMODEL - 1);
    float xn = x[idx] * g_scale;
    float cum = bd[c];
    float w = 0.f;
    #pragma unroll
    for (int j = 0; j < NBLK; ++j) {
        cum += g_G[(size_t)j * (BATCH * DMODEL) + idx];
        float d = cum - xn;
        w = fmaf(bw[j] * d, d, w);
    }
    #pragma unroll
    for (int o = 16; o; o >>= 1) w += __shfl_xor_sync(0xffffffffu, w, o);
    __shared__ float red[8];
    if ((tid & 31) == 0) red[tid >> 5] = w;
    __syncthreads();
    if (tid == 0) {
        float t = 0.f;
        #pragma unroll
        for (int i = 0; i < 8; ++i) t += red[i];
        atomicAdd(&g_msesum, t);
    }
}

// ---------------- final combine ----------------
__global__ void k_final(const int* __restrict__ seg, const float* __restrict__ bw,
                        const float* __restrict__ l1s, float* __restrict__ out) {
    const int tid = threadIdx.x;
    float a[NBLK] = {};
    for (int f = tid; f < NFEAT; f += 256) {
        float v = g_perfeat[f];
        int sg = seg[f];
        #pragma unroll
        for (int k = 0; k < NBLK; ++k)
            if (sg == k) a[k] += v;
    }
    __shared__ float red[8];
    __shared__ float bl[NBLK];
    for (int k = 0; k < NBLK; ++k) {
        float v = a[k];
        #pragma unroll
        for (int o = 16; o; o >>= 1) v += __shfl_xor_sync(0xffffffffu, v, o);
        if ((tid & 31) == 0) red[tid >> 5] = v;
        __syncthreads();
        if (tid == 0) {
            float t = 0.f;
            for (int w = 0; w < 8; ++w) t += red[w];
            bl[k] = t;
        }
        __syncthreads();
    }
    if (tid == 0) {
        float cum = 0.f, l1 = 0.f;
        for (int k = 0; k < NBLK; ++k) { cum += bl[k]; l1 += bw[k] * cum; }
        l1 = l1 / (8.0f * (float)BATCH);
        float mse = g_msesum / (8.0f * (float)BATCH);
        float l0 = (float)g_l0 / (float)BATCH;
        float ls = l1s[0] * (l0 < 100.0f ? (1.0f - 3e-4f) : (1.0f + 3e-4f));
        out[0] = mse + ls * l1;
    }
}

// ---------------- launch ----------------
extern "C" void kernel_launch(void* const* d_in, const int* in_sizes, int n_in,
                              void* d_out, int out_size) {
    const float* x   = (const float*)d_in[0];
    const float* We  = (const float*)d_in[1];
    const float* be  = (const float*)d_in[2];
    const float* Wd  = (const float*)d_in[3];
    const float* bd  = (const float*)d_in[4];
    const float* bw  = (const float*)d_in[5];
    const float* ra  = (const float*)d_in[6];
    const float* l1s = (const float*)d_in[7];
    const int*   seg = (const int*)d_in[8];
    float* out = (float*)d_out;

    k_init<<<128, 256>>>();
    k_zeroG<<<(NBLK * BATCH * DMODEL) / 4 / 256, 256>>>();
    k_wdnorm<<<(NFEAT * 32) / 256, 256>>>(Wd);
    k_rownorm<<<(BATCH * 32) / 256, 256>>>(x);
    k_scale<<<1, 1>>>(ra);
    k_bounds<<<NFEAT / 256, 256>>>(seg);
    k_encoder<<<dim3(NFEAT / 128, BATCH / 128), 256>>>(x, We, be);
    k_decoder<<<dim3(16, 2, 16), 256>>>(Wd);
    k_errs<<<(BATCH * DMODEL) / 256, 256>>>(x, bd, bw);
    k_final<<<1, 256>>>(seg, bw, l1s, out);
}

// round 4
// speedup vs baseline: 4.6560x; 2.0790x over previous
#include <cuda_runtime.h>
#include <math.h>
#include <stdint.h>

#define BATCH  2048
#define DMODEL 256
#define NFEAT  32768
#define NBLK   8

// ---------------- device scratch ----------------
__device__ float g_acts[(size_t)BATCH * NFEAT];          // 256 MiB (tf32-rounded)
__device__ float g_G[(size_t)NBLK * BATCH * DMODEL];     // 16 MiB per-segment deltas
__device__ float g_wdn[NFEAT];
__device__ float g_perfeat[NFEAT];
__device__ float g_msesum;
__device__ unsigned long long g_l0;
__device__ float g_normsum;
__device__ float g_scale;
__device__ int   g_ends[NBLK];

// ---------------- helpers ----------------
__device__ __forceinline__ float f2tf(float f) {
    uint32_t u; asm("cvt.rna.tf32.f32 %0, %1;" : "=r"(u) : "f"(f));
    return __uint_as_float(u);
}
__device__ __forceinline__ void mma_tf32(float* d, const uint32_t* a, const uint32_t* b) {
    asm volatile("mma.sync.aligned.m16n8k8.row.col.f32.tf32.tf32.f32 "
        "{%0,%1,%2,%3}, {%4,%5,%6,%7}, {%8,%9}, {%0,%1,%2,%3};"
        : "+f"(d[0]), "+f"(d[1]), "+f"(d[2]), "+f"(d[3])
        : "r"(a[0]), "r"(a[1]), "r"(a[2]), "r"(a[3]), "r"(b[0]), "r"(b[1]));
}

// ---------------- init ----------------
__global__ void k_init() {
    int i = blockIdx.x * blockDim.x + threadIdx.x;
    if (i < NFEAT) g_perfeat[i] = 0.f;
    if (i == 0) { g_l0 = 0ull; g_normsum = 0.f; g_msesum = 0.f; }
}
__global__ void k_zeroG() {
    size_t i = (size_t)(blockIdx.x * blockDim.x + threadIdx.x) * 4;
    *(float4*)&g_G[i] = make_float4(0.f, 0.f, 0.f, 0.f);
}

// ---------------- W_dec row norms ----------------
__global__ void k_wdnorm(const float* __restrict__ Wd) {
    int warp = (blockIdx.x * blockDim.x + threadIdx.x) >> 5;
    int lane = threadIdx.x & 31;
    if (warp >= NFEAT) return;
    const float* row = Wd + (size_t)warp * DMODEL;
    float s = 0.f;
    #pragma unroll
    for (int i = lane; i < DMODEL; i += 32) { float v = row[i]; s = fmaf(v, v, s); }
    #pragma unroll
    for (int o = 16; o; o >>= 1) s += __shfl_xor_sync(0xffffffffu, s, o);
    if (!lane) g_wdn[warp] = sqrtf(s);
}

// ---------------- sum of row L2 norms of x ----------------
__global__ void k_rownorm(const float* __restrict__ x) {
    int warp = (blockIdx.x * blockDim.x + threadIdx.x) >> 5;
    int lane = threadIdx.x & 31;
    if (warp >= BATCH) return;
    const float* row = x + (size_t)warp * DMODEL;
    float s = 0.f;
    #pragma unroll
    for (int i = lane; i < DMODEL; i += 32) { float v = row[i]; s = fmaf(v, v, s); }
    #pragma unroll
    for (int o = 16; o; o >>= 1) s += __shfl_xor_sync(0xffffffffu, s, o);
    if (!lane) atomicAdd(&g_normsum, sqrtf(s));
}

__global__ void k_scale(const float* __restrict__ ra) {
    float mean = g_normsum / (float)BATCH;
    float r = 0.99f * ra[0] + 0.01f * mean;
    g_scale = 16.0f / r;
}

// ---------------- segment ends ----------------
__global__ void k_bounds(const int* __restrict__ seg) {
    int f = blockIdx.x * blockDim.x + threadIdx.x;
    if (f >= NFEAT) return;
    int s  = seg[f];
    int sn = (f + 1 < NFEAT) ? seg[f + 1] : NBLK;
    for (int j = s; j < sn; j++) g_ends[j] = f + 1;
}

// =====================================================================
// Encoder: tf32 MMA, block 128x128, 4 warps (warp tile 64x64), k-chunk 16,
// double-buffered. Fused relu/log-product/L0 epilogue; stores tf32 acts.
// =====================================================================
__global__ void __launch_bounds__(128, 2) k_encoder(const float* __restrict__ x,
                                                    const float* __restrict__ We,
                                                    const float* __restrict__ be) {
    __shared__ float As[2][16][136];   // [k][m], pad 136 -> conflict-free frag loads
    __shared__ float Bs[2][16][136];   // [k][n]
    __shared__ float colsum[128];
    __shared__ int   redc[4];

    const int tid = threadIdx.x;
    const int lane = tid & 31, wid = tid >> 5;
    const int gid = lane >> 2, tig = lane & 3;
    const int wm0 = (wid >> 1) * 64, wn0 = (wid & 1) * 64;
    const int n0 = blockIdx.x * 128, m0 = blockIdx.y * 128;

    // staging indices
    const int ar = tid >> 2, aq = tid & 3;   // A: 4 threads/row, rows ar+32*it
    const int bk = tid >> 3, bq = tid & 7;   // B: 8 threads/k-row, quads bq+8*it

    float4 fa[4], fb[4];
    auto fetch = [&](int kb) {
        #pragma unroll
        for (int it = 0; it < 4; ++it)
            fa[it] = *(const float4*)&x[(size_t)(m0 + ar + it * 32) * DMODEL + kb + aq * 4];
        #pragma unroll
        for (int it = 0; it < 4; ++it)
            fb[it] = *(const float4*)&We[(size_t)(kb + bk) * NFEAT + n0 + (bq + it * 8) * 4];
    };
    auto stage = [&](int s) {
        #pragma unroll
        for (int it = 0; it < 4; ++it) {
            int r = ar + it * 32;
            As[s][aq * 4 + 0][r] = f2tf(fa[it].x);
            As[s][aq * 4 + 1][r] = f2tf(fa[it].y);
            As[s][aq * 4 + 2][r] = f2tf(fa[it].z);
            As[s][aq * 4 + 3][r] = f2tf(fa[it].w);
        }
        #pragma unroll
        for (int it = 0; it < 4; ++it) {
            float4 v;
            v.x = f2tf(fb[it].x); v.y = f2tf(fb[it].y);
            v.z = f2tf(fb[it].z); v.w = f2tf(fb[it].w);
            *(float4*)&Bs[s][bk][(bq + it * 8) * 4] = v;
        }
    };

    float acc[4][8][4] = {};

    fetch(0); stage(0); __syncthreads();

    #pragma unroll 1
    for (int c = 0; c < 16; ++c) {
        int s = c & 1;
        if (c < 15) fetch((c + 1) * 16);
        #pragma unroll
        for (int ck = 0; ck < 16; ck += 8) {
            uint32_t a[4][4], b[8][2];
            #pragma unroll
            for (int mf = 0; mf < 4; ++mf) {
                int rb = wm0 + mf * 16;
                a[mf][0] = __float_as_uint(As[s][ck + tig][rb + gid]);
                a[mf][1] = __float_as_uint(As[s][ck + tig][rb + gid + 8]);
                a[mf][2] = __float_as_uint(As[s][ck + tig + 4][rb + gid]);
                a[mf][3] = __float_as_uint(As[s][ck + tig + 4][rb + gid + 8]);
            }
            #pragma unroll
            for (int nf = 0; nf < 8; ++nf) {
                int cb = wn0 + nf * 8;
                b[nf][0] = __float_as_uint(Bs[s][ck + tig][cb + gid]);
                b[nf][1] = __float_as_uint(Bs[s][ck + tig + 4][cb + gid]);
            }
            #pragma unroll
            for (int mf = 0; mf < 4; ++mf)
                #pragma unroll
                for (int nf = 0; nf < 8; ++nf)
                    mma_tf32(acc[mf][nf], a[mf], b[nf]);
        }
        if (c < 15) stage(s ^ 1);
        __syncthreads();
    }

    // ---------------- epilogue ----------------
    float sc = g_scale;
    colsum[tid] = 0.f;
    __syncthreads();

    int cnt = 0;
    #pragma unroll
    for (int nf = 0; nf < 8; ++nf) {
        #pragma unroll
        for (int e = 0; e < 2; ++e) {
            int cl = wn0 + nf * 8 + tig * 2 + e;
            int cg = n0 + cl;
            float bias = be[cg];
            float wd10 = g_wdn[cg] * 10.0f;
            float prod = 1.f;
            #pragma unroll
            for (int mf = 0; mf < 4; ++mf) {
                float a1 = fmaxf(fmaf(acc[mf][nf][e], sc, bias), 0.f);
                float a2 = fmaxf(fmaf(acc[mf][nf][2 + e], sc, bias), 0.f);
                acc[mf][nf][e] = a1; acc[mf][nf][2 + e] = a2;
                cnt += (a1 > 0.f) ? 1 : 0;
                cnt += (a2 > 0.f) ? 1 : 0;
                prod *= fmaf(a1, wd10, 1.f) * fmaf(a2, wd10, 1.f);
            }
            atomicAdd(&colsum[cl], __logf(prod));   // sum log = log prod (max ~7^8, safe)
        }
    }
    // store acts, tf32-rounded so decoder can consume without cvt
    #pragma unroll
    for (int mf = 0; mf < 4; ++mf) {
        int r1 = m0 + wm0 + mf * 16 + gid;
        int r2 = r1 + 8;
        #pragma unroll
        for (int nf = 0; nf < 8; ++nf) {
            int cg = n0 + wn0 + nf * 8 + tig * 2;
            float2 v1 = make_float2(f2tf(acc[mf][nf][0]), f2tf(acc[mf][nf][1]));
            float2 v2 = make_float2(f2tf(acc[mf][nf][2]), f2tf(acc[mf][nf][3]));
            *(float2*)&g_acts[(size_t)r1 * NFEAT + cg] = v1;
            *(float2*)&g_acts[(size_t)r2 * NFEAT + cg] = v2;
        }
    }
    __syncthreads();
    atomicAdd(&g_perfeat[n0 + tid], colsum[tid]);

    #pragma unroll
    for (int o = 16; o; o >>= 1) cnt += __shfl_xor_sync(0xffffffffu, cnt, o);
    if (lane == 0) redc[wid] = cnt;
    __syncthreads();
    if (tid == 0) {
        int t = redc[0] + redc[1] + redc[2] + redc[3];
        atomicAdd(&g_l0, (unsigned long long)t);
    }
}

// =====================================================================
// Decoder: tf32 MMA split-K. Grid (KS=16, N=2, M=16). Block 128x128,
// 4 warps, k-chunk 16, double-buffered. Segment-boundary chunks use a
// scalar path on the same fragment-mapped accumulators; flush -> g_G[j].
// =====================================================================
__global__ void __launch_bounds__(128, 2) k_decoder(const float* __restrict__ Wd) {
    __shared__ float As[2][16][136];   // acts [k][m]
    __shared__ float Bs[2][16][136];   // Wd   [k][n]
    __shared__ int   ends_s[9];

    const int tid = threadIdx.x;
    const int lane = tid & 31, wid = tid >> 5;
    const int gid = lane >> 2, tig = lane & 3;
    const int wm0 = (wid >> 1) * 64, wn0 = (wid & 1) * 64;
    const int ks     = blockIdx.x * 2048;
    const int n_base = blockIdx.y * 128;
    const int r_base = blockIdx.z * 128;

    if (tid < 8) ends_s[tid] = g_ends[tid];
    if (tid == 8) ends_s[8] = 0x7fffffff;

    const int ar = tid >> 2, aq = tid & 3;
    const int bk = tid >> 3, bq = tid & 7;

    float4 fa[4], fb[4];
    auto fetch = [&](int kb) {
        #pragma unroll
        for (int it = 0; it < 4; ++it)
            fa[it] = *(const float4*)&g_acts[(size_t)(r_base + ar + it * 32) * NFEAT + kb + aq * 4];
        #pragma unroll
        for (int it = 0; it < 4; ++it)
            fb[it] = *(const float4*)&Wd[(size_t)(kb + bk) * DMODEL + n_base + (bq + it * 8) * 4];
    };
    auto stage = [&](int s) {
        #pragma unroll
        for (int it = 0; it < 4; ++it) {
            int r = ar + it * 32;
            As[s][aq * 4 + 0][r] = fa[it].x;   // already tf32-rounded
            As[s][aq * 4 + 1][r] = fa[it].y;
            As[s][aq * 4 + 2][r] = fa[it].z;
            As[s][aq * 4 + 3][r] = fa[it].w;
        }
        #pragma unroll
        for (int it = 0; it < 4; ++it) {
            float4 v;
            v.x = f2tf(fb[it].x); v.y = f2tf(fb[it].y);
            v.z = f2tf(fb[it].z); v.w = f2tf(fb[it].w);
            *(float4*)&Bs[s][bk][(bq + it * 8) * 4] = v;
        }
    };

    float acc[4][8][4] = {};
    __syncthreads();

    int je = 0;
    while (ends_s[je] <= ks) je++;

    auto flush = [&](int j) {
        float* Gp = g_G + (size_t)j * (BATCH * DMODEL);
        #pragma unroll
        for (int mf = 0; mf < 4; ++mf) {
            int r1 = r_base + wm0 + mf * 16 + gid;
            int r2 = r1 + 8;
            #pragma unroll
            for (int nf = 0; nf < 8; ++nf) {
                int cg = n_base + wn0 + nf * 8 + tig * 2;
                atomicAdd(&Gp[(size_t)r1 * DMODEL + cg],     acc[mf][nf][0]);
                atomicAdd(&Gp[(size_t)r1 * DMODEL + cg + 1], acc[mf][nf][1]);
                atomicAdd(&Gp[(size_t)r2 * DMODEL + cg],     acc[mf][nf][2]);
                atomicAdd(&Gp[(size_t)r2 * DMODEL + cg + 1], acc[mf][nf][3]);
                acc[mf][nf][0] = 0.f; acc[mf][nf][1] = 0.f;
                acc[mf][nf][2] = 0.f; acc[mf][nf][3] = 0.f;
            }
        }
    };

    fetch(ks); stage(0); __syncthreads();

    #pragma unroll 1
    for (int c = 0; c < 128; ++c) {
        int s = c & 1;
        int kb = ks + c * 16;
        if (c < 127) fetch(kb + 16);

        if (ends_s[je] > kb + 16) {
            // hot: pure MMA
            #pragma unroll
            for (int ck = 0; ck < 16; ck += 8) {
                uint32_t a[4][4], b[8][2];
                #pragma unroll
                for (int mf = 0; mf < 4; ++mf) {
                    int rb = wm0 + mf * 16;
                    a[mf][0] = __float_as_uint(As[s][ck + tig][rb + gid]);
                    a[mf][1] = __float_as_uint(As[s][ck + tig][rb + gid + 8]);
                    a[mf][2] = __float_as_uint(As[s][ck + tig + 4][rb + gid]);
                    a[mf][3] = __float_as_uint(As[s][ck + tig + 4][rb + gid + 8]);
                }
                #pragma unroll
                for (int nf = 0; nf < 8; ++nf) {
                    int cb = wn0 + nf * 8;
                    b[nf][0] = __float_as_uint(Bs[s][ck + tig][cb + gid]);
                    b[nf][1] = __float_as_uint(Bs[s][ck + tig + 4][cb + gid]);
                }
                #pragma unroll
                for (int mf = 0; mf < 4; ++mf)
                    #pragma unroll
                    for (int nf = 0; nf < 8; ++nf)
                        mma_tf32(acc[mf][nf], a[mf], b[nf]);
            }
        } else {
            // boundary chunk: scalar per-k on the same fragment mapping (rare)
            for (int kk = 0; kk < 16; ++kk) {
                float av[4][2], bv[8][2];
                #pragma unroll
                for (int mf = 0; mf < 4; ++mf) {
                    int rb = wm0 + mf * 16;
                    av[mf][0] = As[s][kk][rb + gid];
                    av[mf][1] = As[s][kk][rb + gid + 8];
                }
                #pragma unroll
                for (int nf = 0; nf < 8; ++nf) {
                    int cb = wn0 + nf * 8;
                    bv[nf][0] = Bs[s][kk][cb + tig * 2];
                    bv[nf][1] = Bs[s][kk][cb + tig * 2 + 1];
                }
                #pragma unroll
                for (int mf = 0; mf < 4; ++mf)
                    #pragma unroll
                    for (int nf = 0; nf < 8; ++nf) {
                        acc[mf][nf][0] = fmaf(av[mf][0], bv[nf][0], acc[mf][nf][0]);
                        acc[mf][nf][1] = fmaf(av[mf][0], bv[nf][1], acc[mf][nf][1]);
                        acc[mf][nf][2] = fmaf(av[mf][1], bv[nf][0], acc[mf][nf][2]);
                        acc[mf][nf][3] = fmaf(av[mf][1], bv[nf][1], acc[mf][nf][3]);
                    }
                int kg = kb + kk + 1;
                while (ends_s[je] == kg) { flush(je); je++; }
            }
        }
        if (c < 127) stage(s ^ 1);
        __syncthreads();
    }
    if (je < NBLK) flush(je);
}

// ---------------- cumsum over segments + weighted squared error ----------------
__global__ void k_errs(const float* __restrict__ x, const float* __restrict__ bd,
                       const float* __restrict__ bw) {
    const int tid = threadIdx.x;
    int idx = blockIdx.x * 256 + tid;
    int c = idx & (DMODEL - 1);
    float xn = x[idx] * g_scale;
    float cum = bd[c];
    float w = 0.f;
    #pragma unroll
    for (int j = 0; j < NBLK; ++j) {
        cum += g_G[(size_t)j * (BATCH * DMODEL) + idx];
        float d = cum - xn;
        w = fmaf(bw[j] * d, d, w);
    }
    #pragma unroll
    for (int o = 16; o; o >>= 1) w += __shfl_xor_sync(0xffffffffu, w, o);
    __shared__ float red[8];
    if ((tid & 31) == 0) red[tid >> 5] = w;
    __syncthreads();
    if (tid == 0) {
        float t = 0.f;
        #pragma unroll
        for (int i = 0; i < 8; ++i) t += red[i];
        atomicAdd(&g_msesum, t);
    }
}

// ---------------- final combine ----------------
__global__ void k_final(const int* __restrict__ seg, const float* __restrict__ bw,
                        const float* __restrict__ l1s, float* __restrict__ out) {
    const int tid = threadIdx.x;
    float a[NBLK] = {};
    for (int f = tid; f < NFEAT; f += 256) {
        float v = g_perfeat[f];
        int sg = seg[f];
        #pragma unroll
        for (int k = 0; k < NBLK; ++k)
            if (sg == k) a[k] += v;
    }
    __shared__ float red[8];
    __shared__ float bl[NBLK];
    for (int k = 0; k < NBLK; ++k) {
        float v = a[k];
        #pragma unroll
        for (int o = 16; o; o >>= 1) v += __shfl_xor_sync(0xffffffffu, v, o);
        if ((tid & 31) == 0) red[tid >> 5] = v;
        __syncthreads();
        if (tid == 0) {
            float t = 0.f;
            for (int w = 0; w < 8; ++w) t += red[w];
            bl[k] = t;
        }
        __syncthreads();
    }
    if (tid == 0) {
        float cum = 0.f, l1 = 0.f;
        for (int k = 0; k < NBLK; ++k) { cum += bl[k]; l1 += bw[k] * cum; }
        l1 = l1 / (8.0f * (float)BATCH);
        float mse = g_msesum / (8.0f * (float)BATCH);
        float l0 = (float)g_l0 / (float)BATCH;
        float ls = l1s[0] * (l0 < 100.0f ? (1.0f - 3e-4f) : (1.0f + 3e-4f));
        out[0] = mse + ls * l1;
    }
}

// ---------------- launch ----------------
extern "C" void kernel_launch(void* const* d_in, const int* in_sizes, int n_in,
                              void* d_out, int out_size) {
    const float* x   = (const float*)d_in[0];
    const float* We  = (const float*)d_in[1];
    const float* be  = (const float*)d_in[2];
    const float* Wd  = (const float*)d_in[3];
    const float* bd  = (const float*)d_in[4];
    const float* bw  = (const float*)d_in[5];
    const float* ra  = (const float*)d_in[6];
    const float* l1s = (const float*)d_in[7];
    const int*   seg = (const int*)d_in[8];
    float* out = (float*)d_out;

    k_init<<<128, 256>>>();
    k_zeroG<<<(NBLK * BATCH * DMODEL) / 4 / 256, 256>>>();
    k_wdnorm<<<(NFEAT * 32) / 256, 256>>>(Wd);
    k_rownorm<<<(BATCH * 32) / 256, 256>>>(x);
    k_scale<<<1, 1>>>(ra);
    k_bounds<<<NFEAT / 256, 256>>>(seg);
    k_encoder<<<dim3(NFEAT / 128, BATCH / 128), 128>>>(x, We, be);
    k_decoder<<<dim3(16, 2, 16), 128>>>(Wd);
    k_errs<<<(BATCH * DMODEL) / 256, 256>>>(x, bd, bw);
    k_final<<<1, 256>>>(seg, bw, l1s, out);
}

// round 5
// speedup vs baseline: 4.6568x; 1.0002x over previous
#include <cuda_runtime.h>
#include <math.h>
#include <stdint.h>

#define BATCH  2048
#define DMODEL 256
#define NFEAT  32768
#define NBLK   8

// ---------------- device scratch ----------------
__device__ float g_acts[(size_t)BATCH * NFEAT];          // 256 MiB (tf32-rounded)
__device__ float g_G[(size_t)NBLK * BATCH * DMODEL];     // 16 MiB per-segment deltas
__device__ float g_wdn[NFEAT];
__device__ float g_perfeat[NFEAT];
__device__ float g_msesum;
__device__ unsigned long long g_l0;
__device__ float g_normsum;
__device__ float g_scale;
__device__ int   g_ends[NBLK];

// ---------------- helpers ----------------
__device__ __forceinline__ float f2tf(float f) {
    uint32_t u; asm("cvt.rna.tf32.f32 %0, %1;" : "=r"(u) : "f"(f));
    return __uint_as_float(u);
}
__device__ __forceinline__ void mma_tf32(float* d, const uint32_t* a, const uint32_t* b) {
    asm volatile("mma.sync.aligned.m16n8k8.row.col.f32.tf32.tf32.f32 "
        "{%0,%1,%2,%3}, {%4,%5,%6,%7}, {%8,%9}, {%0,%1,%2,%3};"
        : "+f"(d[0]), "+f"(d[1]), "+f"(d[2]), "+f"(d[3])
        : "r"(a[0]), "r"(a[1]), "r"(a[2]), "r"(a[3]), "r"(b[0]), "r"(b[1]));
}

// ---------------- init ----------------
__global__ void k_init() {
    int i = blockIdx.x * blockDim.x + threadIdx.x;
    if (i < NFEAT) g_perfeat[i] = 0.f;
    if (i == 0) { g_l0 = 0ull; g_normsum = 0.f; g_msesum = 0.f; }
}
__global__ void k_zeroG() {
    size_t i = (size_t)(blockIdx.x * blockDim.x + threadIdx.x) * 4;
    *(float4*)&g_G[i] = make_float4(0.f, 0.f, 0.f, 0.f);
}

// ---------------- W_dec row norms ----------------
__global__ void k_wdnorm(const float* __restrict__ Wd) {
    int warp = (blockIdx.x * blockDim.x + threadIdx.x) >> 5;
    int lane = threadIdx.x & 31;
    if (warp >= NFEAT) return;
    const float* row = Wd + (size_t)warp * DMODEL;
    float s = 0.f;
    #pragma unroll
    for (int i = lane; i < DMODEL; i += 32) { float v = row[i]; s = fmaf(v, v, s); }
    #pragma unroll
    for (int o = 16; o; o >>= 1) s += __shfl_xor_sync(0xffffffffu, s, o);
    if (!lane) g_wdn[warp] = sqrtf(s);
}

// ---------------- sum of row L2 norms of x ----------------
__global__ void k_rownorm(const float* __restrict__ x) {
    int warp = (blockIdx.x * blockDim.x + threadIdx.x) >> 5;
    int lane = threadIdx.x & 31;
    if (warp >= BATCH) return;
    const float* row = x + (size_t)warp * DMODEL;
    float s = 0.f;
    #pragma unroll
    for (int i = lane; i < DMODEL; i += 32) { float v = row[i]; s = fmaf(v, v, s); }
    #pragma unroll
    for (int o = 16; o; o >>= 1) s += __shfl_xor_sync(0xffffffffu, s, o);
    if (!lane) atomicAdd(&g_normsum, sqrtf(s));
}

__global__ void k_scale(const float* __restrict__ ra) {
    float mean = g_normsum / (float)BATCH;
    float r = 0.99f * ra[0] + 0.01f * mean;
    g_scale = 16.0f / r;
}

// ---------------- segment ends ----------------
__global__ void k_bounds(const int* __restrict__ seg) {
    int f = blockIdx.x * blockDim.x + threadIdx.x;
    if (f >= NFEAT) return;
    int s  = seg[f];
    int sn = (f + 1 < NFEAT) ? seg[f + 1] : NBLK;
    for (int j = s; j < sn; j++) g_ends[j] = f + 1;
}

// =====================================================================
// Encoder: tf32 MMA, block 128x128, 4 warps (warp tile 64x64), k-chunk 16,
// double-buffered. Fused relu/log-product/L0 epilogue; stores tf32 acts.
// =====================================================================
__global__ void __launch_bounds__(128, 2) k_encoder(const float* __restrict__ x,
                                                    const float* __restrict__ We,
                                                    const float* __restrict__ be) {
    __shared__ float As[2][16][136];   // [k][m], pad 136 -> conflict-free frag loads
    __shared__ float Bs[2][16][136];   // [k][n]
    __shared__ float colsum[128];
    __shared__ int   redc[4];

    const int tid = threadIdx.x;
    const int lane = tid & 31, wid = tid >> 5;
    const int gid = lane >> 2, tig = lane & 3;
    const int wm0 = (wid >> 1) * 64, wn0 = (wid & 1) * 64;
    const int n0 = blockIdx.x * 128, m0 = blockIdx.y * 128;

    // staging indices
    const int ar = tid >> 2, aq = tid & 3;   // A: 4 threads/row, rows ar+32*it
    const int bk = tid >> 3, bq = tid & 7;   // B: 8 threads/k-row, quads bq+8*it

    float4 fa[4], fb[4];
    auto fetch = [&](int kb) {
        #pragma unroll
        for (int it = 0; it < 4; ++it)
            fa[it] = *(const float4*)&x[(size_t)(m0 + ar + it * 32) * DMODEL + kb + aq * 4];
        #pragma unroll
        for (int it = 0; it < 4; ++it)
            fb[it] = *(const float4*)&We[(size_t)(kb + bk) * NFEAT + n0 + (bq + it * 8) * 4];
    };
    auto stage = [&](int s) {
        #pragma unroll
        for (int it = 0; it < 4; ++it) {
            int r = ar + it * 32;
            As[s][aq * 4 + 0][r] = f2tf(fa[it].x);
            As[s][aq * 4 + 1][r] = f2tf(fa[it].y);
            As[s][aq * 4 + 2][r] = f2tf(fa[it].z);
            As[s][aq * 4 + 3][r] = f2tf(fa[it].w);
        }
        #pragma unroll
        for (int it = 0; it < 4; ++it) {
            float4 v;
            v.x = f2tf(fb[it].x); v.y = f2tf(fb[it].y);
            v.z = f2tf(fb[it].z); v.w = f2tf(fb[it].w);
            *(float4*)&Bs[s][bk][(bq + it * 8) * 4] = v;
        }
    };

    float acc[4][8][4] = {};

    fetch(0); stage(0); __syncthreads();

    #pragma unroll 1
    for (int c = 0; c < 16; ++c) {
        int s = c & 1;
        if (c < 15) fetch((c + 1) * 16);
        #pragma unroll
        for (int ck = 0; ck < 16; ck += 8) {
            uint32_t a[4][4], b[8][2];
            #pragma unroll
            for (int mf = 0; mf < 4; ++mf) {
                int rb = wm0 + mf * 16;
                a[mf][0] = __float_as_uint(As[s][ck + tig][rb + gid]);
                a[mf][1] = __float_as_uint(As[s][ck + tig][rb + gid + 8]);
                a[mf][2] = __float_as_uint(As[s][ck + tig + 4][rb + gid]);
                a[mf][3] = __float_as_uint(As[s][ck + tig + 4][rb + gid + 8]);
            }
            #pragma unroll
            for (int nf = 0; nf < 8; ++nf) {
                int cb = wn0 + nf * 8;
                b[nf][0] = __float_as_uint(Bs[s][ck + tig][cb + gid]);
                b[nf][1] = __float_as_uint(Bs[s][ck + tig + 4][cb + gid]);
            }
            #pragma unroll
            for (int mf = 0; mf < 4; ++mf)
                #pragma unroll
                for (int nf = 0; nf < 8; ++nf)
                    mma_tf32(acc[mf][nf], a[mf], b[nf]);
        }
        if (c < 15) stage(s ^ 1);
        __syncthreads();
    }

    // ---------------- epilogue ----------------
    float sc = g_scale;
    colsum[tid] = 0.f;
    __syncthreads();

    int cnt = 0;
    #pragma unroll
    for (int nf = 0; nf < 8; ++nf) {
        #pragma unroll
        for (int e = 0; e < 2; ++e) {
            int cl = wn0 + nf * 8 + tig * 2 + e;
            int cg = n0 + cl;
            float bias = be[cg];
            float wd10 = g_wdn[cg] * 10.0f;
            float prod = 1.f;
            #pragma unroll
            for (int mf = 0; mf < 4; ++mf) {
                float a1 = fmaxf(fmaf(acc[mf][nf][e], sc, bias), 0.f);
                float a2 = fmaxf(fmaf(acc[mf][nf][2 + e], sc, bias), 0.f);
                acc[mf][nf][e] = a1; acc[mf][nf][2 + e] = a2;
                cnt += (a1 > 0.f) ? 1 : 0;
                cnt += (a2 > 0.f) ? 1 : 0;
                prod *= fmaf(a1, wd10, 1.f) * fmaf(a2, wd10, 1.f);
            }
            atomicAdd(&colsum[cl], __logf(prod));   // sum log = log prod (max ~7^8, safe)
        }
    }
    // store acts, tf32-rounded so decoder can consume without cvt
    #pragma unroll
    for (int mf = 0; mf < 4; ++mf) {
        int r1 = m0 + wm0 + mf * 16 + gid;
        int r2 = r1 + 8;
        #pragma unroll
        for (int nf = 0; nf < 8; ++nf) {
            int cg = n0 + wn0 + nf * 8 + tig * 2;
            float2 v1 = make_float2(f2tf(acc[mf][nf][0]), f2tf(acc[mf][nf][1]));
            float2 v2 = make_float2(f2tf(acc[mf][nf][2]), f2tf(acc[mf][nf][3]));
            *(float2*)&g_acts[(size_t)r1 * NFEAT + cg] = v1;
            *(float2*)&g_acts[(size_t)r2 * NFEAT + cg] = v2;
        }
    }
    __syncthreads();
    atomicAdd(&g_perfeat[n0 + tid], colsum[tid]);

    #pragma unroll
    for (int o = 16; o; o >>= 1) cnt += __shfl_xor_sync(0xffffffffu, cnt, o);
    if (lane == 0) redc[wid] = cnt;
    __syncthreads();
    if (tid == 0) {
        int t = redc[0] + redc[1] + redc[2] + redc[3];
        atomicAdd(&g_l0, (unsigned long long)t);
    }
}

// =====================================================================
// Decoder: tf32 MMA split-K. Grid (KS=16, N=2, M=16). Block 128x128,
// 4 warps, k-chunk 16, double-buffered. Segment-boundary chunks use a
// scalar path on the same fragment-mapped accumulators; flush -> g_G[j].
// =====================================================================
__global__ void __launch_bounds__(128, 2) k_decoder(const float* __restrict__ Wd) {
    __shared__ float As[2][16][136];   // acts [k][m]
    __shared__ float Bs[2][16][136];   // Wd   [k][n]
    __shared__ int   ends_s[9];

    const int tid = threadIdx.x;
    const int lane = tid & 31, wid = tid >> 5;
    const int gid = lane >> 2, tig = lane & 3;
    const int wm0 = (wid >> 1) * 64, wn0 = (wid & 1) * 64;
    const int ks     = blockIdx.x * 2048;
    const int n_base = blockIdx.y * 128;
    const int r_base = blockIdx.z * 128;

    if (tid < 8) ends_s[tid] = g_ends[tid];
    if (tid == 8) ends_s[8] = 0x7fffffff;

    const int ar = tid >> 2, aq = tid & 3;
    const int bk = tid >> 3, bq = tid & 7;

    float4 fa[4], fb[4];
    auto fetch = [&](int kb) {
        #pragma unroll
        for (int it = 0; it < 4; ++it)
            fa[it] = *(const float4*)&g_acts[(size_t)(r_base + ar + it * 32) * NFEAT + kb + aq * 4];
        #pragma unroll
        for (int it = 0; it < 4; ++it)
            fb[it] = *(const float4*)&Wd[(size_t)(kb + bk) * DMODEL + n_base + (bq + it * 8) * 4];
    };
    auto stage = [&](int s) {
        #pragma unroll
        for (int it = 0; it < 4; ++it) {
            int r = ar + it * 32;
            As[s][aq * 4 + 0][r] = fa[it].x;   // already tf32-rounded
            As[s][aq * 4 + 1][r] = fa[it].y;
            As[s][aq * 4 + 2][r] = fa[it].z;
            As[s][aq * 4 + 3][r] = fa[it].w;
        }
        #pragma unroll
        for (int it = 0; it < 4; ++it) {
            float4 v;
            v.x = f2tf(fb[it].x); v.y = f2tf(fb[it].y);
            v.z = f2tf(fb[it].z); v.w = f2tf(fb[it].w);
            *(float4*)&Bs[s][bk][(bq + it * 8) * 4] = v;
        }
    };

    float acc[4][8][4] = {};
    __syncthreads();

    int je = 0;
    while (ends_s[je] <= ks) je++;

    auto flush = [&](int j) {
        float* Gp = g_G + (size_t)j * (BATCH * DMODEL);
        #pragma unroll
        for (int mf = 0; mf < 4; ++mf) {
            int r1 = r_base + wm0 + mf * 16 + gid;
            int r2 = r1 + 8;
            #pragma unroll
            for (int nf = 0; nf < 8; ++nf) {
                int cg = n_base + wn0 + nf * 8 + tig * 2;
                atomicAdd(&Gp[(size_t)r1 * DMODEL + cg],     acc[mf][nf][0]);
                atomicAdd(&Gp[(size_t)r1 * DMODEL + cg + 1], acc[mf][nf][1]);
                atomicAdd(&Gp[(size_t)r2 * DMODEL + cg],     acc[mf][nf][2]);
                atomicAdd(&Gp[(size_t)r2 * DMODEL + cg + 1], acc[mf][nf][3]);
                acc[mf][nf][0] = 0.f; acc[mf][nf][1] = 0.f;
                acc[mf][nf][2] = 0.f; acc[mf][nf][3] = 0.f;
            }
        }
    };

    fetch(ks); stage(0); __syncthreads();

    #pragma unroll 1
    for (int c = 0; c < 128; ++c) {
        int s = c & 1;
        int kb = ks + c * 16;
        if (c < 127) fetch(kb + 16);

        if (ends_s[je] > kb + 16) {
            // hot: pure MMA
            #pragma unroll
            for (int ck = 0; ck < 16; ck += 8) {
                uint32_t a[4][4], b[8][2];
                #pragma unroll
                for (int mf = 0; mf < 4; ++mf) {
                    int rb = wm0 + mf * 16;
                    a[mf][0] = __float_as_uint(As[s][ck + tig][rb + gid]);
                    a[mf][1] = __float_as_uint(As[s][ck + tig][rb + gid + 8]);
                    a[mf][2] = __float_as_uint(As[s][ck + tig + 4][rb + gid]);
                    a[mf][3] = __float_as_uint(As[s][ck + tig + 4][rb + gid + 8]);
                }
                #pragma unroll
                for (int nf = 0; nf < 8; ++nf) {
                    int cb = wn0 + nf * 8;
                    b[nf][0] = __float_as_uint(Bs[s][ck + tig][cb + gid]);
                    b[nf][1] = __float_as_uint(Bs[s][ck + tig + 4][cb + gid]);
                }
                #pragma unroll
                for (int mf = 0; mf < 4; ++mf)
                    #pragma unroll
                    for (int nf = 0; nf < 8; ++nf)
                        mma_tf32(acc[mf][nf], a[mf], b[nf]);
            }
        } else {
            // boundary chunk: scalar per-k on the same fragment mapping (rare)
            for (int kk = 0; kk < 16; ++kk) {
                float av[4][2], bv[8][2];
                #pragma unroll
                for (int mf = 0; mf < 4; ++mf) {
                    int rb = wm0 + mf * 16;
                    av[mf][0] = As[s][kk][rb + gid];
                    av[mf][1] = As[s][kk][rb + gid + 8];
                }
                #pragma unroll
                for (int nf = 0; nf < 8; ++nf) {
                    int cb = wn0 + nf * 8;
                    bv[nf][0] = Bs[s][kk][cb + tig * 2];
                    bv[nf][1] = Bs[s][kk][cb + tig * 2 + 1];
                }
                #pragma unroll
                for (int mf = 0; mf < 4; ++mf)
                    #pragma unroll
                    for (int nf = 0; nf < 8; ++nf) {
                        acc[mf][nf][0] = fmaf(av[mf][0], bv[nf][0], acc[mf][nf][0]);
                        acc[mf][nf][1] = fmaf(av[mf][0], bv[nf][1], acc[mf][nf][1]);
                        acc[mf][nf][2] = fmaf(av[mf][1], bv[nf][0], acc[mf][nf][2]);
                        acc[mf][nf][3] = fmaf(av[mf][1], bv[nf][1], acc[mf][nf][3]);
                    }
                int kg = kb + kk + 1;
                while (ends_s[je] == kg) { flush(je); je++; }
            }
        }
        if (c < 127) stage(s ^ 1);
        __syncthreads();
    }
    if (je < NBLK) flush(je);
}

// ---------------- cumsum over segments + weighted squared error ----------------
__global__ void k_errs(const float* __restrict__ x, const float* __restrict__ bd,
                       const float* __restrict__ bw) {
    const int tid = threadIdx.x;
    int idx = blockIdx.x * 256 + tid;
    int c = idx & (DMODEL - 1);
    float xn = x[idx] * g_scale;
    float cum = bd[c];
    float w = 0.f;
    #pragma unroll
    for (int j = 0; j < NBLK; ++j) {
        cum += g_G[(size_t)j * (BATCH * DMODEL) + idx];
        float d = cum - xn;
        w = fmaf(bw[j] * d, d, w);
    }
    #pragma unroll
    for (int o = 16; o; o >>= 1) w += __shfl_xor_sync(0xffffffffu, w, o);
    __shared__ float red[8];
    if ((tid & 31) == 0) red[tid >> 5] = w;
    __syncthreads();
    if (tid == 0) {
        float t = 0.f;
        #pragma unroll
        for (int i = 0; i < 8; ++i) t += red[i];
        atomicAdd(&g_msesum, t);
    }
}

// ---------------- final combine ----------------
__global__ void k_final(const int* __restrict__ seg, const float* __restrict__ bw,
                        const float* __restrict__ l1s, float* __restrict__ out) {
    const int tid = threadIdx.x;
    float a[NBLK] = {};
    for (int f = tid; f < NFEAT; f += 256) {
        float v = g_perfeat[f];
        int sg = seg[f];
        #pragma unroll
        for (int k = 0; k < NBLK; ++k)
            if (sg == k) a[k] += v;
    }
    __shared__ float red[8];
    __shared__ float bl[NBLK];
    for (int k = 0; k < NBLK; ++k) {
        float v = a[k];
        #pragma unroll
        for (int o = 16; o; o >>= 1) v += __shfl_xor_sync(0xffffffffu, v, o);
        if ((tid & 31) == 0) red[tid >> 5] = v;
        __syncthreads();
        if (tid == 0) {
            float t = 0.f;
            for (int w = 0; w < 8; ++w) t += red[w];
            bl[k] = t;
        }
        __syncthreads();
    }
    if (tid == 0) {
        float cum = 0.f, l1 = 0.f;
        for (int k = 0; k < NBLK; ++k) { cum += bl[k]; l1 += bw[k] * cum; }
        l1 = l1 / (8.0f * (float)BATCH);
        float mse = g_msesum / (8.0f * (float)BATCH);
        float l0 = (float)g_l0 / (float)BATCH;
        float ls = l1s[0] * (l0 < 100.0f ? (1.0f - 3e-4f) : (1.0f + 3e-4f));
        out[0] = mse + ls * l1;
    }
}

// ---------------- launch ----------------
extern "C" void kernel_launch(void* const* d_in, const int* in_sizes, int n_in,
                              void* d_out, int out_size) {
    const float* x   = (const float*)d_in[0];
    const float* We  = (const float*)d_in[1];
    const float* be  = (const float*)d_in[2];
    const float* Wd  = (const float*)d_in[3];
    const float* bd  = (const float*)d_in[4];
    const float* bw  = (const float*)d_in[5];
    const float* ra  = (const float*)d_in[6];
    const float* l1s = (const float*)d_in[7];
    const int*   seg = (const int*)d_in[8];
    float* out = (float*)d_out;

    k_init<<<128, 256>>>();
    k_zeroG<<<(NBLK * BATCH * DMODEL) / 4 / 256, 256>>>();
    k_wdnorm<<<(NFEAT * 32) / 256, 256>>>(Wd);
    k_rownorm<<<(BATCH * 32) / 256, 256>>>(x);
    k_scale<<<1, 1>>>(ra);
    k_bounds<<<NFEAT / 256, 256>>>(seg);
    k_encoder<<<dim3(NFEAT / 128, BATCH / 128), 128>>>(x, We, be);
    k_decoder<<<dim3(16, 2, 16), 128>>>(Wd);
    k_errs<<<(BATCH * DMODEL) / 256, 256>>>(x, bd, bw);
    k_final<<<1, 256>>>(seg, bw, l1s, out);
}